// round 5
// baseline (speedup 1.0000x reference)
#include <cuda_runtime.h>
#include <cuda_bf16.h>
#include <cstdint>

// Problem shapes
#define TOK   1024
#define HDIM  1024
#define FDIM  3584
#define NEXP  8

// Tiling
#define BM 128
#define BN 64
#define BK 32
#define MAXROWS  3072
#define MAXTILES (MAXROWS / BM)
#define NSM   148
#define GEMM_GRID (2 * NSM)

// ---------------- device scratch ----------------
__device__ uint32_t g_act[(size_t)MAXROWS * FDIM];  // packed (hi | lo<<16) bf16
__device__ uint32_t g_xpk[(size_t)TOK * HDIM];      // packed hidden_states
__device__ int    g_ptok[MAXROWS];
__device__ float  g_pw[MAXROWS];
__device__ int    g_tile_expert[MAXTILES];
__device__ int    g_nRowTiles;
__device__ int2   g_topi[TOK];
__device__ float2 g_topw[TOK];

// 64B-row swizzle: XOR bits[5:4] with bits[8:7] -> conflict-free ldmatrix
#define SWZ64(o) ((o) ^ (((o) >> 3) & 0x30))

__device__ __forceinline__ void ldmx4(uint32_t* r, uint32_t a) {
    asm volatile("ldmatrix.sync.aligned.m8n8.x4.shared.b16 {%0,%1,%2,%3}, [%4];"
                 : "=r"(r[0]), "=r"(r[1]), "=r"(r[2]), "=r"(r[3]) : "r"(a));
}
__device__ __forceinline__ void mma_bf16(float* d, const uint32_t* a, const uint32_t* b) {
    asm volatile("mma.sync.aligned.m16n8k16.row.col.f32.bf16.bf16.f32 "
                 "{%0,%1,%2,%3}, {%4,%5,%6,%7}, {%8,%9}, {%0,%1,%2,%3};"
                 : "+f"(d[0]), "+f"(d[1]), "+f"(d[2]), "+f"(d[3])
                 : "r"(a[0]), "r"(a[1]), "r"(a[2]), "r"(a[3]), "r"(b[0]), "r"(b[1]));
}

// fp32x4 -> bf16 hi/lo planes (packed as 2x uint2)
__device__ __forceinline__ void split4(float4 v, uint2& hp, uint2& lp) {
    __nv_bfloat16 h0 = __float2bfloat16_rn(v.x), h1 = __float2bfloat16_rn(v.y);
    __nv_bfloat16 h2 = __float2bfloat16_rn(v.z), h3 = __float2bfloat16_rn(v.w);
    __nv_bfloat16 l0 = __float2bfloat16_rn(v.x - __bfloat162float(h0));
    __nv_bfloat16 l1 = __float2bfloat16_rn(v.y - __bfloat162float(h1));
    __nv_bfloat16 l2 = __float2bfloat16_rn(v.z - __bfloat162float(h2));
    __nv_bfloat16 l3 = __float2bfloat16_rn(v.w - __bfloat162float(h3));
    hp.x = (uint32_t)__bfloat16_as_ushort(h0) | ((uint32_t)__bfloat16_as_ushort(h1) << 16);
    hp.y = (uint32_t)__bfloat16_as_ushort(h2) | ((uint32_t)__bfloat16_as_ushort(h3) << 16);
    lp.x = (uint32_t)__bfloat16_as_ushort(l0) | ((uint32_t)__bfloat16_as_ushort(l1) << 16);
    lp.y = (uint32_t)__bfloat16_as_ushort(l2) | ((uint32_t)__bfloat16_as_ushort(l3) << 16);
}
__device__ __forceinline__ uint32_t pack_hl(float v) {
    __nv_bfloat16 h = __float2bfloat16_rn(v);
    __nv_bfloat16 l = __float2bfloat16_rn(v - __bfloat162float(h));
    return (uint32_t)__bfloat16_as_ushort(h) | ((uint32_t)__bfloat16_as_ushort(l) << 16);
}
// packed u32x4 -> hi/lo uint2
__device__ __forceinline__ void unpack4(uint4 v, uint2& hp, uint2& lp) {
    hp.x = (v.x & 0xffffu) | (v.y << 16);
    hp.y = (v.z & 0xffffu) | (v.w << 16);
    lp.x = (v.x >> 16) | (v.y & 0xffff0000u);
    lp.y = (v.z >> 16) | (v.w & 0xffff0000u);
}
__device__ __forceinline__ float silumul(float h1, float h3) {
    return (h1 / (1.f + __expf(-h1))) * h3;
}

// ---------------- router (also packs x into hi/lo planes) ----------------
__global__ void router_kernel(const float* __restrict__ x,
                              const float* __restrict__ gw,
                              float* __restrict__ out,
                              float* __restrict__ logits) {
    const int t = blockIdx.x;
    const int tid = threadIdx.x;
    const float* xr = x + (size_t)t * HDIM;

    float acc[NEXP];
#pragma unroll
    for (int e = 0; e < NEXP; e++) acc[e] = 0.f;
    for (int h = tid; h < HDIM; h += 128) {
        float xv = xr[h];
        g_xpk[(size_t)t * HDIM + h] = pack_hl(xv);
#pragma unroll
        for (int e = 0; e < NEXP; e++) acc[e] += xv * gw[e * HDIM + h];
    }
    __shared__ float red[NEXP][128];
#pragma unroll
    for (int e = 0; e < NEXP; e++) red[e][tid] = acc[e];
    __syncthreads();
    for (int s = 64; s > 0; s >>= 1) {
        if (tid < s) {
#pragma unroll
            for (int e = 0; e < NEXP; e++) red[e][tid] += red[e][tid + s];
        }
        __syncthreads();
    }
    float* orow = out + (size_t)t * HDIM;
    for (int h = tid; h < HDIM; h += 128) orow[h] = 0.f;

    if (tid == 0) {
        float lg[NEXP];
        float mx = -1e30f;
#pragma unroll
        for (int e = 0; e < NEXP; e++) {
            lg[e] = red[e][0];
            logits[t * NEXP + e] = lg[e];
            mx = fmaxf(mx, lg[e]);
        }
        float pe[NEXP];
#pragma unroll
        for (int e = 0; e < NEXP; e++) pe[e] = expf(lg[e] - mx);
        int i1 = 0;
#pragma unroll
        for (int e = 1; e < NEXP; e++) if (pe[e] > pe[i1]) i1 = e;
        int i2 = (i1 == 0) ? 1 : 0;
#pragma unroll
        for (int e = 0; e < NEXP; e++) if (e != i2 && e != i1 && pe[e] > pe[i2]) i2 = e;
        float p1 = pe[i1], p2 = pe[i2];
        float inv = 1.f / (p1 + p2);
        g_topi[t] = make_int2(i1, i2);
        g_topw[t] = make_float2(p1 * inv, p2 * inv);
    }
}

// ---------------- token lists ----------------
__global__ void build_lists() {
    const int tid = threadIdx.x;
    __shared__ int2 stop[TOK];
    __shared__ float2 stw[TOK];
    __shared__ int cnt[NEXP], off[NEXP], pad[NEXP];

    for (int t = tid; t < TOK; t += 64) { stop[t] = g_topi[t]; stw[t] = g_topw[t]; }
    __syncthreads();
    if (tid < NEXP) {
        int c = 0;
        for (int t = 0; t < TOK; t++) {
            int2 ti = stop[t];
            if (ti.x == tid || ti.y == tid) c++;
        }
        cnt[tid] = c;
    }
    __syncthreads();
    if (tid == 0) {
        int o = 0;
        for (int e = 0; e < NEXP; e++) {
            off[e] = o;
            pad[e] = (cnt[e] + BM - 1) & ~(BM - 1);
            for (int tt = o / BM; tt < (o + pad[e]) / BM; tt++) g_tile_expert[tt] = e;
            o += pad[e];
        }
        g_nRowTiles = o / BM;
    }
    __syncthreads();
    if (tid < NEXP) {
        const int e = tid;
        int pos = off[e];
        for (int t = 0; t < TOK; t++) {
            int2 ti = stop[t];
            if (ti.x == e)      { g_ptok[pos] = t; g_pw[pos] = stw[t].x; pos++; }
            else if (ti.y == e) { g_ptok[pos] = t; g_pw[pos] = stw[t].y; pos++; }
        }
        const int end = off[e] + pad[e];
        for (; pos < end; pos++) { g_ptok[pos] = 0; g_pw[pos] = 0.f; }
    }
}

// ================= fused w1/w3 kernel (persistent) =================
// Stage layout (bytes): AHI 0, ALO 8K, B1HI 16K, B1LO 20K, B3HI 24K, B3LO 28K
#define ST1   32768
#define SM13  (1024 + 2 * ST1)
#define AHI   0
#define ALO   8192
#define B1HI  16384
#define B1LO  20480
#define B3HI  24576
#define B3LO  28672
#define NC1   (HDIM / BK)   // 32

__global__ void __launch_bounds__(256, 2)
moe_gemm13(const float* __restrict__ w1,
           const float* __restrict__ w3) {
    extern __shared__ char smem[];
    const int tid = threadIdx.x, wid = tid >> 5, lane = tid & 31;
    const int wm = wid & 3, wn = wid >> 2;
    int* s_tok = (int*)smem;

    const int nRT = g_nRowTiles;
    const int total = (FDIM / BN) * nRT;

    // per-thread constant roles
    const int arow = tid >> 1, acol = (tid & 1) * 16;
    const int brow = tid >> 2, bcol = (tid & 3) * 8;
    uint32_t aoff[4], boff[2];
#pragma unroll
    for (int j = 0; j < 4; j++) aoff[j] = SWZ64((uint32_t)(arow * 64 + (acol + j * 4) * 2));
#pragma unroll
    for (int j = 0; j < 2; j++) boff[j] = SWZ64((uint32_t)(brow * 64 + (bcol + j * 4) * 2));

    for (int tile = blockIdx.x; tile < total; tile += gridDim.x) {
        const int nt = tile / nRT, rt = tile - nt * nRT;
        const int e  = g_tile_expert[rt];
        const int n0 = nt * BN;
        const int r0 = rt * BM;

        __syncthreads();   // protect s_tok from previous tile's readers
        if (tid < BM) s_tok[tid] = g_ptok[r0 + tid];
        __syncthreads();

        const float* w1e = w1 + (size_t)e * FDIM * HDIM;
        const float* w3e = w3 + (size_t)e * FDIM * HDIM;
        const uint32_t* aptr = g_xpk + (size_t)s_tok[arow] * HDIM + acol;
        const float* b1p = w1e + (size_t)(n0 + brow) * HDIM + bcol;
        const float* b3p = w3e + (size_t)(n0 + brow) * HDIM + bcol;

        uint4 aR[4]; float4 b1R[2], b3R[2];

        // prologue: chunk 0 -> stage 0
#pragma unroll
        for (int j = 0; j < 4; j++) aR[j] = *(const uint4*)(aptr + j * 4);
#pragma unroll
        for (int j = 0; j < 2; j++) { b1R[j] = *(const float4*)(b1p + j * 4); b3R[j] = *(const float4*)(b3p + j * 4); }
        {
            char* st = smem + 1024;
            uint2 hp, lp;
#pragma unroll
            for (int j = 0; j < 4; j++) { unpack4(aR[j], hp, lp); *(uint2*)(st + AHI + aoff[j]) = hp; *(uint2*)(st + ALO + aoff[j]) = lp; }
#pragma unroll
            for (int j = 0; j < 2; j++) {
                split4(b1R[j], hp, lp); *(uint2*)(st + B1HI + boff[j]) = hp; *(uint2*)(st + B1LO + boff[j]) = lp;
                split4(b3R[j], hp, lp); *(uint2*)(st + B3HI + boff[j]) = hp; *(uint2*)(st + B3LO + boff[j]) = lp;
            }
        }
        __syncthreads();

        float a1[2][4][4], a3[2][4][4];
#pragma unroll
        for (int m = 0; m < 2; m++)
#pragma unroll
            for (int n = 0; n < 4; n++)
#pragma unroll
                for (int q = 0; q < 4; q++) { a1[m][n][q] = 0.f; a3[m][n][q] = 0.f; }

        for (int c = 0; c < NC1; c++) {
            if (c + 1 < NC1) {
                const int kn = (c + 1) * BK;
#pragma unroll
                for (int j = 0; j < 4; j++) aR[j] = *(const uint4*)(aptr + kn + j * 4);
#pragma unroll
                for (int j = 0; j < 2; j++) { b1R[j] = *(const float4*)(b1p + kn + j * 4); b3R[j] = *(const float4*)(b3p + kn + j * 4); }
            }
            uint32_t sb = (uint32_t)__cvta_generic_to_shared(smem + 1024 + (c & 1) * ST1);
#pragma unroll
            for (int s = 0; s < 2; s++) {
                const int ks = s * 16;
                uint32_t ah[2][4], al[2][4];
#pragma unroll
                for (int mt = 0; mt < 2; mt++) {
                    uint32_t ro = SWZ64((uint32_t)((wm * 32 + mt * 16 + (lane & 15)) * 64 + (ks + (lane >> 4) * 8) * 2));
                    ldmx4(ah[mt], sb + AHI + ro);
                    ldmx4(al[mt], sb + ALO + ro);
                }
                uint32_t b1h[2][4], b1l[2][4], b3h[2][4], b3l[2][4];
#pragma unroll
                for (int np = 0; np < 2; np++) {
                    uint32_t ro = SWZ64((uint32_t)((wn * 32 + np * 16 + ((lane >> 4) & 1) * 8 + (lane & 7)) * 64 +
                                                   (ks + ((lane >> 3) & 1) * 8) * 2));
                    ldmx4(b1h[np], sb + B1HI + ro);
                    ldmx4(b1l[np], sb + B1LO + ro);
                    ldmx4(b3h[np], sb + B3HI + ro);
                    ldmx4(b3l[np], sb + B3LO + ro);
                }
#pragma unroll
                for (int mt = 0; mt < 2; mt++)
#pragma unroll
                    for (int np = 0; np < 2; np++)
#pragma unroll
                        for (int h = 0; h < 2; h++) {
                            const int nt2 = np * 2 + h;
                            mma_bf16(a1[mt][nt2], ah[mt], &b1h[np][h * 2]);
                            mma_bf16(a1[mt][nt2], ah[mt], &b1l[np][h * 2]);
                            mma_bf16(a1[mt][nt2], al[mt], &b1h[np][h * 2]);
                            mma_bf16(a3[mt][nt2], ah[mt], &b3h[np][h * 2]);
                            mma_bf16(a3[mt][nt2], ah[mt], &b3l[np][h * 2]);
                            mma_bf16(a3[mt][nt2], al[mt], &b3h[np][h * 2]);
                        }
            }
            if (c + 1 < NC1) {
                // store into the OTHER buffer: its previous readers finished before
                // the barrier that ended iteration c-1 -> no mid-loop barrier needed.
                char* st = smem + 1024 + ((c + 1) & 1) * ST1;
                uint2 hp, lp;
#pragma unroll
                for (int j = 0; j < 4; j++) { unpack4(aR[j], hp, lp); *(uint2*)(st + AHI + aoff[j]) = hp; *(uint2*)(st + ALO + aoff[j]) = lp; }
#pragma unroll
                for (int j = 0; j < 2; j++) {
                    split4(b1R[j], hp, lp); *(uint2*)(st + B1HI + boff[j]) = hp; *(uint2*)(st + B1LO + boff[j]) = lp;
                    split4(b3R[j], hp, lp); *(uint2*)(st + B3HI + boff[j]) = hp; *(uint2*)(st + B3LO + boff[j]) = lp;
                }
            }
            __syncthreads();
        }

        // epilogue: act = silu(h1)*h3 packed hi/lo -> g_act
#pragma unroll
        for (int mt = 0; mt < 2; mt++)
#pragma unroll
            for (int nt2 = 0; nt2 < 4; nt2++) {
                const int row = r0 + wm * 32 + mt * 16 + (lane >> 2);
                const int col = n0 + wn * 32 + nt2 * 8 + 2 * (lane & 3);
                uint2 v;
                v.x = pack_hl(silumul(a1[mt][nt2][0], a3[mt][nt2][0]));
                v.y = pack_hl(silumul(a1[mt][nt2][1], a3[mt][nt2][1]));
                *(uint2*)(g_act + (size_t)row * FDIM + col) = v;
                v.x = pack_hl(silumul(a1[mt][nt2][2], a3[mt][nt2][2]));
                v.y = pack_hl(silumul(a1[mt][nt2][3], a3[mt][nt2][3]));
                *(uint2*)(g_act + (size_t)(row + 8) * FDIM + col) = v;
            }
    }
}

// ================= w2 kernel (persistent) =================
// Stage layout: AHI 0, ALO 8K, BHI 16K, BLO 20K
#define ST2   24576
#define SM2   (1024 + 2 * ST2)
#define BHI2  16384
#define BLO2  20480
#define NC2   (FDIM / BK)   // 112

__global__ void __launch_bounds__(256, 2)
moe_gemm2(const float* __restrict__ w2, float* __restrict__ out) {
    extern __shared__ char smem[];
    const int tid = threadIdx.x, wid = tid >> 5, lane = tid & 31;
    const int wm = wid & 3, wn = wid >> 2;
    int*   s_tok = (int*)smem;
    float* s_w   = (float*)(smem + 512);

    const int nRT = g_nRowTiles;
    const int total = (HDIM / BN) * nRT;

    const int arow = tid >> 1, acol = (tid & 1) * 16;
    const int brow = tid >> 2, bcol = (tid & 3) * 8;
    uint32_t aoff[4], boff[2];
#pragma unroll
    for (int j = 0; j < 4; j++) aoff[j] = SWZ64((uint32_t)(arow * 64 + (acol + j * 4) * 2));
#pragma unroll
    for (int j = 0; j < 2; j++) boff[j] = SWZ64((uint32_t)(brow * 64 + (bcol + j * 4) * 2));

    for (int tile = blockIdx.x; tile < total; tile += gridDim.x) {
        const int nt = tile / nRT, rt = tile - nt * nRT;
        const int e  = g_tile_expert[rt];
        const int n0 = nt * BN;
        const int r0 = rt * BM;

        __syncthreads();   // protect s_tok/s_w from previous tile's epilogue readers
        if (tid < BM) { s_tok[tid] = g_ptok[r0 + tid]; s_w[tid] = g_pw[r0 + tid]; }
        __syncthreads();

        const float* w2e = w2 + (size_t)e * HDIM * FDIM;
        const uint32_t* aptr = g_act + (size_t)(r0 + arow) * FDIM + acol;
        const float* bp = w2e + (size_t)(n0 + brow) * FDIM + bcol;

        uint4 aR[4]; float4 bR[2];
#pragma unroll
        for (int j = 0; j < 4; j++) aR[j] = *(const uint4*)(aptr + j * 4);
#pragma unroll
        for (int j = 0; j < 2; j++) bR[j] = *(const float4*)(bp + j * 4);
        {
            char* st = smem + 1024;
            uint2 hp, lp;
#pragma unroll
            for (int j = 0; j < 4; j++) { unpack4(aR[j], hp, lp); *(uint2*)(st + AHI + aoff[j]) = hp; *(uint2*)(st + ALO + aoff[j]) = lp; }
#pragma unroll
            for (int j = 0; j < 2; j++) { split4(bR[j], hp, lp); *(uint2*)(st + BHI2 + boff[j]) = hp; *(uint2*)(st + BLO2 + boff[j]) = lp; }
        }
        __syncthreads();

        float acc[2][4][4];
#pragma unroll
        for (int m = 0; m < 2; m++)
#pragma unroll
            for (int n = 0; n < 4; n++)
#pragma unroll
                for (int q = 0; q < 4; q++) acc[m][n][q] = 0.f;

        for (int c = 0; c < NC2; c++) {
            if (c + 1 < NC2) {
                const int kn = (c + 1) * BK;
#pragma unroll
                for (int j = 0; j < 4; j++) aR[j] = *(const uint4*)(aptr + kn + j * 4);
#pragma unroll
                for (int j = 0; j < 2; j++) bR[j] = *(const float4*)(bp + kn + j * 4);
            }
            uint32_t sb = (uint32_t)__cvta_generic_to_shared(smem + 1024 + (c & 1) * ST2);
#pragma unroll
            for (int s = 0; s < 2; s++) {
                const int ks = s * 16;
                uint32_t ah[2][4], al[2][4];
#pragma unroll
                for (int mt = 0; mt < 2; mt++) {
                    uint32_t ro = SWZ64((uint32_t)((wm * 32 + mt * 16 + (lane & 15)) * 64 + (ks + (lane >> 4) * 8) * 2));
                    ldmx4(ah[mt], sb + AHI + ro);
                    ldmx4(al[mt], sb + ALO + ro);
                }
                uint32_t bh[2][4], bl[2][4];
#pragma unroll
                for (int np = 0; np < 2; np++) {
                    uint32_t ro = SWZ64((uint32_t)((wn * 32 + np * 16 + ((lane >> 4) & 1) * 8 + (lane & 7)) * 64 +
                                                   (ks + ((lane >> 3) & 1) * 8) * 2));
                    ldmx4(bh[np], sb + BHI2 + ro);
                    ldmx4(bl[np], sb + BLO2 + ro);
                }
#pragma unroll
                for (int mt = 0; mt < 2; mt++)
#pragma unroll
                    for (int np = 0; np < 2; np++)
#pragma unroll
                        for (int h = 0; h < 2; h++) {
                            const int nt2 = np * 2 + h;
                            mma_bf16(acc[mt][nt2], ah[mt], &bh[np][h * 2]);
                            mma_bf16(acc[mt][nt2], ah[mt], &bl[np][h * 2]);
                            mma_bf16(acc[mt][nt2], al[mt], &bh[np][h * 2]);
                        }
            }
            if (c + 1 < NC2) {
                char* st = smem + 1024 + ((c + 1) & 1) * ST2;
                uint2 hp, lp;
#pragma unroll
                for (int j = 0; j < 4; j++) { unpack4(aR[j], hp, lp); *(uint2*)(st + AHI + aoff[j]) = hp; *(uint2*)(st + ALO + aoff[j]) = lp; }
#pragma unroll
                for (int j = 0; j < 2; j++) { split4(bR[j], hp, lp); *(uint2*)(st + BHI2 + boff[j]) = hp; *(uint2*)(st + BLO2 + boff[j]) = lp; }
            }
            __syncthreads();
        }

        // epilogue: weighted atomic combine
#pragma unroll
        for (int mt = 0; mt < 2; mt++) {
            const int lr0 = wm * 32 + mt * 16 + (lane >> 2);
            const int tok0 = s_tok[lr0];     const float wt0 = s_w[lr0];
            const int tok1 = s_tok[lr0 + 8]; const float wt1 = s_w[lr0 + 8];
#pragma unroll
            for (int nt2 = 0; nt2 < 4; nt2++) {
                const int col = n0 + wn * 32 + nt2 * 8 + 2 * (lane & 3);
                float* o0 = out + (size_t)tok0 * HDIM + col;
                float* o1 = out + (size_t)tok1 * HDIM + col;
                atomicAdd(o0,     wt0 * acc[mt][nt2][0]);
                atomicAdd(o0 + 1, wt0 * acc[mt][nt2][1]);
                atomicAdd(o1,     wt1 * acc[mt][nt2][2]);
                atomicAdd(o1 + 1, wt1 * acc[mt][nt2][3]);
            }
        }
    }
}

// ---------------- launch ----------------
extern "C" void kernel_launch(void* const* d_in, const int* in_sizes, int n_in,
                              void* d_out, int out_size) {
    const float* x  = (const float*)d_in[0];
    const float* gw = (const float*)d_in[1];
    const float* w1 = (const float*)d_in[2];
    const float* w2 = (const float*)d_in[3];
    const float* w3 = (const float*)d_in[4];

    float* out    = (float*)d_out;
    float* logits = out + (size_t)TOK * HDIM;

    cudaFuncSetAttribute(moe_gemm13, cudaFuncAttributeMaxDynamicSharedMemorySize, SM13);
    cudaFuncSetAttribute(moe_gemm2,  cudaFuncAttributeMaxDynamicSharedMemorySize, SM2);

    router_kernel<<<TOK, 128>>>(x, gw, out, logits);
    build_lists<<<1, 64>>>();
    moe_gemm13<<<GEMM_GRID, 256, SM13>>>(w1, w3);
    moe_gemm2<<<GEMM_GRID, 256, SM2>>>(w2, out);
}

// round 6
// speedup vs baseline: 1.2080x; 1.2080x over previous
#include <cuda_runtime.h>
#include <cuda_bf16.h>
#include <cstdint>

// Problem shapes
#define TOK   1024
#define HDIM  1024
#define FDIM  3584
#define NEXP  8

// Tiling
#define BM 128
#define BN 64
#define BK 32
#define MAXROWS  3072
#define MAXTILES (MAXROWS / BM)

// ---------------- device scratch ----------------
__device__ __nv_bfloat16 g_xh[(size_t)TOK * HDIM];      // x hi plane
__device__ __nv_bfloat16 g_xl[(size_t)TOK * HDIM];      // x lo plane
__device__ __nv_bfloat16 g_ah[(size_t)MAXROWS * FDIM];  // act hi plane
__device__ __nv_bfloat16 g_al[(size_t)MAXROWS * FDIM];  // act lo plane
__device__ int    g_ptok[MAXROWS];
__device__ float  g_pw[MAXROWS];
__device__ int    g_tile_expert[MAXTILES];
__device__ int    g_nRowTiles;
__device__ int2   g_topi[TOK];
__device__ float2 g_topw[TOK];

// 64B-row swizzle: XOR bits[5:4] with bits[8:7] -> conflict-free ldmatrix
#define SWZ64(o) ((o) ^ (((o) >> 3) & 0x30))

__device__ __forceinline__ void ldmx4(uint32_t* r, uint32_t a) {
    asm volatile("ldmatrix.sync.aligned.m8n8.x4.shared.b16 {%0,%1,%2,%3}, [%4];"
                 : "=r"(r[0]), "=r"(r[1]), "=r"(r[2]), "=r"(r[3]) : "r"(a));
}
__device__ __forceinline__ void mma_bf16(float* d, const uint32_t* a, const uint32_t* b) {
    asm volatile("mma.sync.aligned.m16n8k16.row.col.f32.bf16.bf16.f32 "
                 "{%0,%1,%2,%3}, {%4,%5,%6,%7}, {%8,%9}, {%0,%1,%2,%3};"
                 : "+f"(d[0]), "+f"(d[1]), "+f"(d[2]), "+f"(d[3])
                 : "r"(a[0]), "r"(a[1]), "r"(a[2]), "r"(a[3]), "r"(b[0]), "r"(b[1]));
}
__device__ __forceinline__ void cpa16(uint32_t dst, const void* src) {
    asm volatile("cp.async.cg.shared.global [%0], [%1], 16;" :: "r"(dst), "l"(src));
}
#define CP_COMMIT() asm volatile("cp.async.commit_group;" ::: "memory")
#define CP_WAIT0()  asm volatile("cp.async.wait_group 0;" ::: "memory")

// fp32x4 -> bf16 hi/lo planes (packed as 2x uint2)
__device__ __forceinline__ void split4(float4 v, uint2& hp, uint2& lp) {
    __nv_bfloat16 h0 = __float2bfloat16_rn(v.x), h1 = __float2bfloat16_rn(v.y);
    __nv_bfloat16 h2 = __float2bfloat16_rn(v.z), h3 = __float2bfloat16_rn(v.w);
    __nv_bfloat16 l0 = __float2bfloat16_rn(v.x - __bfloat162float(h0));
    __nv_bfloat16 l1 = __float2bfloat16_rn(v.y - __bfloat162float(h1));
    __nv_bfloat16 l2 = __float2bfloat16_rn(v.z - __bfloat162float(h2));
    __nv_bfloat16 l3 = __float2bfloat16_rn(v.w - __bfloat162float(h3));
    hp.x = (uint32_t)__bfloat16_as_ushort(h0) | ((uint32_t)__bfloat16_as_ushort(h1) << 16);
    hp.y = (uint32_t)__bfloat16_as_ushort(h2) | ((uint32_t)__bfloat16_as_ushort(h3) << 16);
    lp.x = (uint32_t)__bfloat16_as_ushort(l0) | ((uint32_t)__bfloat16_as_ushort(l1) << 16);
    lp.y = (uint32_t)__bfloat16_as_ushort(l2) | ((uint32_t)__bfloat16_as_ushort(l3) << 16);
}
__device__ __forceinline__ void store_hl2(__nv_bfloat16* ph, __nv_bfloat16* pl,
                                          float v0, float v1) {
    __nv_bfloat16 h0 = __float2bfloat16_rn(v0), h1 = __float2bfloat16_rn(v1);
    __nv_bfloat16 l0 = __float2bfloat16_rn(v0 - __bfloat162float(h0));
    __nv_bfloat16 l1 = __float2bfloat16_rn(v1 - __bfloat162float(h1));
    *(uint32_t*)ph = (uint32_t)__bfloat16_as_ushort(h0) | ((uint32_t)__bfloat16_as_ushort(h1) << 16);
    *(uint32_t*)pl = (uint32_t)__bfloat16_as_ushort(l0) | ((uint32_t)__bfloat16_as_ushort(l1) << 16);
}
__device__ __forceinline__ float silumul(float h1, float h3) {
    return (h1 / (1.f + __expf(-h1))) * h3;
}

// ---------------- router (also writes x hi/lo planes) ----------------
__global__ void router_kernel(const float* __restrict__ x,
                              const float* __restrict__ gw,
                              float* __restrict__ out,
                              float* __restrict__ logits) {
    const int t = blockIdx.x;
    const int tid = threadIdx.x;
    const float* xr = x + (size_t)t * HDIM;

    float acc[NEXP];
#pragma unroll
    for (int e = 0; e < NEXP; e++) acc[e] = 0.f;
    for (int h = tid; h < HDIM; h += 128) {
        float xv = xr[h];
        __nv_bfloat16 hb = __float2bfloat16_rn(xv);
        g_xh[(size_t)t * HDIM + h] = hb;
        g_xl[(size_t)t * HDIM + h] = __float2bfloat16_rn(xv - __bfloat162float(hb));
#pragma unroll
        for (int e = 0; e < NEXP; e++) acc[e] += xv * gw[e * HDIM + h];
    }
    __shared__ float red[NEXP][128];
#pragma unroll
    for (int e = 0; e < NEXP; e++) red[e][tid] = acc[e];
    __syncthreads();
    for (int s = 64; s > 0; s >>= 1) {
        if (tid < s) {
#pragma unroll
            for (int e = 0; e < NEXP; e++) red[e][tid] += red[e][tid + s];
        }
        __syncthreads();
    }
    float* orow = out + (size_t)t * HDIM;
    for (int h = tid; h < HDIM; h += 128) orow[h] = 0.f;

    if (tid == 0) {
        float lg[NEXP];
        float mx = -1e30f;
#pragma unroll
        for (int e = 0; e < NEXP; e++) {
            lg[e] = red[e][0];
            logits[t * NEXP + e] = lg[e];
            mx = fmaxf(mx, lg[e]);
        }
        float pe[NEXP];
#pragma unroll
        for (int e = 0; e < NEXP; e++) pe[e] = expf(lg[e] - mx);
        int i1 = 0;
#pragma unroll
        for (int e = 1; e < NEXP; e++) if (pe[e] > pe[i1]) i1 = e;
        int i2 = (i1 == 0) ? 1 : 0;
#pragma unroll
        for (int e = 0; e < NEXP; e++) if (e != i2 && e != i1 && pe[e] > pe[i2]) i2 = e;
        float p1 = pe[i1], p2 = pe[i2];
        float inv = 1.f / (p1 + p2);
        g_topi[t] = make_int2(i1, i2);
        g_topw[t] = make_float2(p1 * inv, p2 * inv);
    }
}

// ---------------- token lists ----------------
__global__ void build_lists() {
    const int tid = threadIdx.x;
    __shared__ int2 stop[TOK];
    __shared__ float2 stw[TOK];
    __shared__ int cnt[NEXP], off[NEXP], pad[NEXP];

    for (int t = tid; t < TOK; t += 64) { stop[t] = g_topi[t]; stw[t] = g_topw[t]; }
    __syncthreads();
    if (tid < NEXP) {
        int c = 0;
        for (int t = 0; t < TOK; t++) {
            int2 ti = stop[t];
            if (ti.x == tid || ti.y == tid) c++;
        }
        cnt[tid] = c;
    }
    __syncthreads();
    if (tid == 0) {
        int o = 0;
        for (int e = 0; e < NEXP; e++) {
            off[e] = o;
            pad[e] = (cnt[e] + BM - 1) & ~(BM - 1);
            for (int tt = o / BM; tt < (o + pad[e]) / BM; tt++) g_tile_expert[tt] = e;
            o += pad[e];
        }
        g_nRowTiles = o / BM;
    }
    __syncthreads();
    if (tid < NEXP) {
        const int e = tid;
        int pos = off[e];
        for (int t = 0; t < TOK; t++) {
            int2 ti = stop[t];
            if (ti.x == e)      { g_ptok[pos] = t; g_pw[pos] = stw[t].x; pos++; }
            else if (ti.y == e) { g_ptok[pos] = t; g_pw[pos] = stw[t].y; pos++; }
        }
        const int end = off[e] + pad[e];
        for (; pos < end; pos++) { g_ptok[pos] = 0; g_pw[pos] = 0.f; }
    }
}

// ================= fused w1/w3 kernel =================
// Stage layout (bytes): AHI 0, ALO 8K, B1HI 16K, B1LO 20K, B3HI 24K, B3LO 28K
#define ST1   32768
#define SM13  (1024 + 2 * ST1)
#define AHI   0
#define ALO   8192
#define B1HI  16384
#define B1LO  20480
#define B3HI  24576
#define B3LO  28672
#define NC1   (HDIM / BK)   // 32

__global__ void __launch_bounds__(256, 2)
moe_gemm13(const float* __restrict__ w1,
           const float* __restrict__ w3) {
    const int rt = blockIdx.y;
    if (rt >= g_nRowTiles) return;
    extern __shared__ char smem[];
    const uint32_t sbase = (uint32_t)__cvta_generic_to_shared(smem) + 1024;
    const int tid = threadIdx.x, wid = tid >> 5, lane = tid & 31;
    const int wm = wid & 3, wn = wid >> 2;
    const int e  = g_tile_expert[rt];
    const int n0 = blockIdx.x * BN;
    const int r0 = rt * BM;

    int* s_tok = (int*)smem;
    if (tid < BM) s_tok[tid] = g_ptok[r0 + tid];
    __syncthreads();

    const float* w1e = w1 + (size_t)e * FDIM * HDIM;
    const float* w3e = w3 + (size_t)e * FDIM * HDIM;

    // A cp.async role: thread -> (row = tid>>1, segs {0,1} or {2,3})
    const int arow = tid >> 1;
    const int aseg = (tid & 1) * 2;
    const __nv_bfloat16* axh = g_xh + (size_t)s_tok[arow] * HDIM + aseg * 8;
    const __nv_bfloat16* axl = g_xl + (size_t)s_tok[arow] * HDIM + aseg * 8;
    const uint32_t ad0 = SWZ64((uint32_t)(arow * 64 + aseg * 16));
    const uint32_t ad1 = SWZ64((uint32_t)(arow * 64 + aseg * 16 + 16));

    // B staging role
    const int brow = tid >> 2, bcol = (tid & 3) * 8;
    const float* b1p = w1e + (size_t)(n0 + brow) * HDIM + bcol;
    const float* b3p = w3e + (size_t)(n0 + brow) * HDIM + bcol;
    uint32_t boff[2];
#pragma unroll
    for (int j = 0; j < 2; j++) boff[j] = SWZ64((uint32_t)(brow * 64 + (bcol + j * 4) * 2));

    float4 b1R[2], b3R[2];

    // prologue: chunk 0 -> stage 0
    {
        uint32_t st = sbase;
        cpa16(st + AHI + ad0, axh);
        cpa16(st + AHI + ad1, axh + 8);
        cpa16(st + ALO + ad0, axl);
        cpa16(st + ALO + ad1, axl + 8);
        CP_COMMIT();
#pragma unroll
        for (int j = 0; j < 2; j++) { b1R[j] = *(const float4*)(b1p + j * 4); b3R[j] = *(const float4*)(b3p + j * 4); }
        char* stc = smem + 1024;
        uint2 hp, lp;
#pragma unroll
        for (int j = 0; j < 2; j++) {
            split4(b1R[j], hp, lp); *(uint2*)(stc + B1HI + boff[j]) = hp; *(uint2*)(stc + B1LO + boff[j]) = lp;
            split4(b3R[j], hp, lp); *(uint2*)(stc + B3HI + boff[j]) = hp; *(uint2*)(stc + B3LO + boff[j]) = lp;
        }
        CP_WAIT0();
    }
    __syncthreads();

    float a1[2][4][4], a3[2][4][4];
#pragma unroll
    for (int m = 0; m < 2; m++)
#pragma unroll
        for (int n = 0; n < 4; n++)
#pragma unroll
            for (int q = 0; q < 4; q++) { a1[m][n][q] = 0.f; a3[m][n][q] = 0.f; }

    for (int c = 0; c < NC1; c++) {
        if (c + 1 < NC1) {
            const int kn = (c + 1) * BK;
            uint32_t st = sbase + ((c + 1) & 1) * ST1;
            cpa16(st + AHI + ad0, axh + kn);
            cpa16(st + AHI + ad1, axh + kn + 8);
            cpa16(st + ALO + ad0, axl + kn);
            cpa16(st + ALO + ad1, axl + kn + 8);
            CP_COMMIT();
#pragma unroll
            for (int j = 0; j < 2; j++) { b1R[j] = *(const float4*)(b1p + kn + j * 4); b3R[j] = *(const float4*)(b3p + kn + j * 4); }
        }
        uint32_t sb = sbase + (c & 1) * ST1;
#pragma unroll
        for (int s = 0; s < 2; s++) {
            const int ks = s * 16;
            uint32_t ah[2][4], al[2][4];
#pragma unroll
            for (int mt = 0; mt < 2; mt++) {
                uint32_t ro = SWZ64((uint32_t)((wm * 32 + mt * 16 + (lane & 15)) * 64 + (ks + (lane >> 4) * 8) * 2));
                ldmx4(ah[mt], sb + AHI + ro);
                ldmx4(al[mt], sb + ALO + ro);
            }
            uint32_t b1h[2][4], b1l[2][4], b3h[2][4], b3l[2][4];
#pragma unroll
            for (int np = 0; np < 2; np++) {
                uint32_t ro = SWZ64((uint32_t)((wn * 32 + np * 16 + ((lane >> 4) & 1) * 8 + (lane & 7)) * 64 +
                                               (ks + ((lane >> 3) & 1) * 8) * 2));
                ldmx4(b1h[np], sb + B1HI + ro);
                ldmx4(b1l[np], sb + B1LO + ro);
                ldmx4(b3h[np], sb + B3HI + ro);
                ldmx4(b3l[np], sb + B3LO + ro);
            }
#pragma unroll
            for (int mt = 0; mt < 2; mt++)
#pragma unroll
                for (int np = 0; np < 2; np++)
#pragma unroll
                    for (int h = 0; h < 2; h++) {
                        const int nt2 = np * 2 + h;
                        mma_bf16(a1[mt][nt2], ah[mt], &b1h[np][h * 2]);
                        mma_bf16(a1[mt][nt2], ah[mt], &b1l[np][h * 2]);
                        mma_bf16(a1[mt][nt2], al[mt], &b1h[np][h * 2]);
                        mma_bf16(a3[mt][nt2], ah[mt], &b3h[np][h * 2]);
                        mma_bf16(a3[mt][nt2], ah[mt], &b3l[np][h * 2]);
                        mma_bf16(a3[mt][nt2], al[mt], &b3h[np][h * 2]);
                    }
        }
        if (c + 1 < NC1) {
            // store into the OTHER buffer; its previous readers finished before the
            // barrier that ended iteration c-1 -> single sync per chunk is sufficient.
            char* stc = smem + 1024 + ((c + 1) & 1) * ST1;
            uint2 hp, lp;
#pragma unroll
            for (int j = 0; j < 2; j++) {
                split4(b1R[j], hp, lp); *(uint2*)(stc + B1HI + boff[j]) = hp; *(uint2*)(stc + B1LO + boff[j]) = lp;
                split4(b3R[j], hp, lp); *(uint2*)(stc + B3HI + boff[j]) = hp; *(uint2*)(stc + B3LO + boff[j]) = lp;
            }
        }
        CP_WAIT0();
        __syncthreads();
    }

    // epilogue: act = silu(h1)*h3 -> hi/lo planes
#pragma unroll
    for (int mt = 0; mt < 2; mt++)
#pragma unroll
        for (int nt2 = 0; nt2 < 4; nt2++) {
            const int row = r0 + wm * 32 + mt * 16 + (lane >> 2);
            const int col = n0 + wn * 32 + nt2 * 8 + 2 * (lane & 3);
            store_hl2(g_ah + (size_t)row * FDIM + col, g_al + (size_t)row * FDIM + col,
                      silumul(a1[mt][nt2][0], a3[mt][nt2][0]),
                      silumul(a1[mt][nt2][1], a3[mt][nt2][1]));
            store_hl2(g_ah + (size_t)(row + 8) * FDIM + col, g_al + (size_t)(row + 8) * FDIM + col,
                      silumul(a1[mt][nt2][2], a3[mt][nt2][2]),
                      silumul(a1[mt][nt2][3], a3[mt][nt2][3]));
        }
}

// ================= w2 kernel =================
// Stage layout: AHI 0, ALO 8K, BHI 16K, BLO 20K
#define ST2   24576
#define SM2   (1024 + 2 * ST2)
#define BHI2  16384
#define BLO2  20480
#define NC2   (FDIM / BK)   // 112

__global__ void __launch_bounds__(256, 2)
moe_gemm2(const float* __restrict__ w2, float* __restrict__ out) {
    const int rt = blockIdx.y;
    if (rt >= g_nRowTiles) return;
    extern __shared__ char smem[];
    const uint32_t sbase = (uint32_t)__cvta_generic_to_shared(smem) + 1024;
    const int tid = threadIdx.x, wid = tid >> 5, lane = tid & 31;
    const int wm = wid & 3, wn = wid >> 2;
    const int e  = g_tile_expert[rt];
    const int n0 = blockIdx.x * BN;
    const int r0 = rt * BM;

    int*   s_tok = (int*)smem;
    float* s_w   = (float*)(smem + 512);
    if (tid < BM) { s_tok[tid] = g_ptok[r0 + tid]; s_w[tid] = g_pw[r0 + tid]; }
    __syncthreads();

    const float* w2e = w2 + (size_t)e * HDIM * FDIM;

    const int arow = tid >> 1;
    const int aseg = (tid & 1) * 2;
    const __nv_bfloat16* aph = g_ah + (size_t)(r0 + arow) * FDIM + aseg * 8;
    const __nv_bfloat16* apl = g_al + (size_t)(r0 + arow) * FDIM + aseg * 8;
    const uint32_t ad0 = SWZ64((uint32_t)(arow * 64 + aseg * 16));
    const uint32_t ad1 = SWZ64((uint32_t)(arow * 64 + aseg * 16 + 16));

    const int brow = tid >> 2, bcol = (tid & 3) * 8;
    const float* bp = w2e + (size_t)(n0 + brow) * FDIM + bcol;
    uint32_t boff[2];
#pragma unroll
    for (int j = 0; j < 2; j++) boff[j] = SWZ64((uint32_t)(brow * 64 + (bcol + j * 4) * 2));

    float4 bR[2];

    // prologue
    {
        uint32_t st = sbase;
        cpa16(st + AHI + ad0, aph);
        cpa16(st + AHI + ad1, aph + 8);
        cpa16(st + ALO + ad0, apl);
        cpa16(st + ALO + ad1, apl + 8);
        CP_COMMIT();
#pragma unroll
        for (int j = 0; j < 2; j++) bR[j] = *(const float4*)(bp + j * 4);
        char* stc = smem + 1024;
        uint2 hp, lp;
#pragma unroll
        for (int j = 0; j < 2; j++) { split4(bR[j], hp, lp); *(uint2*)(stc + BHI2 + boff[j]) = hp; *(uint2*)(stc + BLO2 + boff[j]) = lp; }
        CP_WAIT0();
    }
    __syncthreads();

    float acc[2][4][4];
#pragma unroll
    for (int m = 0; m < 2; m++)
#pragma unroll
        for (int n = 0; n < 4; n++)
#pragma unroll
            for (int q = 0; q < 4; q++) acc[m][n][q] = 0.f;

    for (int c = 0; c < NC2; c++) {
        if (c + 1 < NC2) {
            const int kn = (c + 1) * BK;
            uint32_t st = sbase + ((c + 1) & 1) * ST2;
            cpa16(st + AHI + ad0, aph + kn);
            cpa16(st + AHI + ad1, aph + kn + 8);
            cpa16(st + ALO + ad0, apl + kn);
            cpa16(st + ALO + ad1, apl + kn + 8);
            CP_COMMIT();
#pragma unroll
            for (int j = 0; j < 2; j++) bR[j] = *(const float4*)(bp + kn + j * 4);
        }
        uint32_t sb = sbase + (c & 1) * ST2;
#pragma unroll
        for (int s = 0; s < 2; s++) {
            const int ks = s * 16;
            uint32_t ah[2][4], al[2][4];
#pragma unroll
            for (int mt = 0; mt < 2; mt++) {
                uint32_t ro = SWZ64((uint32_t)((wm * 32 + mt * 16 + (lane & 15)) * 64 + (ks + (lane >> 4) * 8) * 2));
                ldmx4(ah[mt], sb + AHI + ro);
                ldmx4(al[mt], sb + ALO + ro);
            }
            uint32_t bh[2][4], bl[2][4];
#pragma unroll
            for (int np = 0; np < 2; np++) {
                uint32_t ro = SWZ64((uint32_t)((wn * 32 + np * 16 + ((lane >> 4) & 1) * 8 + (lane & 7)) * 64 +
                                               (ks + ((lane >> 3) & 1) * 8) * 2));
                ldmx4(bh[np], sb + BHI2 + ro);
                ldmx4(bl[np], sb + BLO2 + ro);
            }
#pragma unroll
            for (int mt = 0; mt < 2; mt++)
#pragma unroll
                for (int np = 0; np < 2; np++)
#pragma unroll
                    for (int h = 0; h < 2; h++) {
                        const int nt2 = np * 2 + h;
                        mma_bf16(acc[mt][nt2], ah[mt], &bh[np][h * 2]);
                        mma_bf16(acc[mt][nt2], ah[mt], &bl[np][h * 2]);
                        mma_bf16(acc[mt][nt2], al[mt], &bh[np][h * 2]);
                    }
        }
        if (c + 1 < NC2) {
            char* stc = smem + 1024 + ((c + 1) & 1) * ST2;
            uint2 hp, lp;
#pragma unroll
            for (int j = 0; j < 2; j++) { split4(bR[j], hp, lp); *(uint2*)(stc + BHI2 + boff[j]) = hp; *(uint2*)(stc + BLO2 + boff[j]) = lp; }
        }
        CP_WAIT0();
        __syncthreads();
    }

    // epilogue: weighted atomic combine
#pragma unroll
    for (int mt = 0; mt < 2; mt++) {
        const int lr0 = wm * 32 + mt * 16 + (lane >> 2);
        const int tok0 = s_tok[lr0];     const float wt0 = s_w[lr0];
        const int tok1 = s_tok[lr0 + 8]; const float wt1 = s_w[lr0 + 8];
#pragma unroll
        for (int nt2 = 0; nt2 < 4; nt2++) {
            const int col = n0 + wn * 32 + nt2 * 8 + 2 * (lane & 3);
            float* o0 = out + (size_t)tok0 * HDIM + col;
            float* o1 = out + (size_t)tok1 * HDIM + col;
            atomicAdd(o0,     wt0 * acc[mt][nt2][0]);
            atomicAdd(o0 + 1, wt0 * acc[mt][nt2][1]);
            atomicAdd(o1,     wt1 * acc[mt][nt2][2]);
            atomicAdd(o1 + 1, wt1 * acc[mt][nt2][3]);
        }
    }
}

// ---------------- launch ----------------
extern "C" void kernel_launch(void* const* d_in, const int* in_sizes, int n_in,
                              void* d_out, int out_size) {
    const float* x  = (const float*)d_in[0];
    const float* gw = (const float*)d_in[1];
    const float* w1 = (const float*)d_in[2];
    const float* w2 = (const float*)d_in[3];
    const float* w3 = (const float*)d_in[4];

    float* out    = (float*)d_out;
    float* logits = out + (size_t)TOK * HDIM;

    cudaFuncSetAttribute(moe_gemm13, cudaFuncAttributeMaxDynamicSharedMemorySize, SM13);
    cudaFuncSetAttribute(moe_gemm2,  cudaFuncAttributeMaxDynamicSharedMemorySize, SM2);

    router_kernel<<<TOK, 128>>>(x, gw, out, logits);
    build_lists<<<1, 64>>>();
    moe_gemm13<<<dim3(FDIM / BN, MAXTILES), 256, SM13>>>(w1, w3);
    moe_gemm2<<<dim3(HDIM / BN, MAXTILES), 256, SM2>>>(w2, out);
}

// round 7
// speedup vs baseline: 1.2203x; 1.0101x over previous
#include <cuda_runtime.h>
#include <cuda_bf16.h>
#include <cstdint>

// Problem shapes
#define TOK   1024
#define HDIM  1024
#define FDIM  3584
#define NEXP  8

// Tiling
#define BM 128
#define BN 64
#define BK 32
#define MAXROWS  3072
#define MAXTILES (MAXROWS / BM)

// ---------------- device scratch ----------------
__device__ __nv_bfloat16 g_xh[(size_t)TOK * HDIM];      // x hi plane
__device__ __nv_bfloat16 g_xl[(size_t)TOK * HDIM];      // x lo plane
__device__ __nv_bfloat16 g_ah[(size_t)MAXROWS * FDIM];  // act hi plane
__device__ __nv_bfloat16 g_al[(size_t)MAXROWS * FDIM];  // act lo plane
__device__ int    g_ptok[MAXROWS];
__device__ float  g_pw[MAXROWS];
__device__ int    g_tile_expert[MAXTILES];
__device__ int    g_nRowTiles;
__device__ int2   g_topi[TOK];
__device__ float2 g_topw[TOK];

// 64B-row swizzle: XOR bits[5:4] with bits[8:7] -> conflict-free ldmatrix
#define SWZ64(o) ((o) ^ (((o) >> 3) & 0x30))

__device__ __forceinline__ void ldmx4(uint32_t* r, uint32_t a) {
    asm volatile("ldmatrix.sync.aligned.m8n8.x4.shared.b16 {%0,%1,%2,%3}, [%4];"
                 : "=r"(r[0]), "=r"(r[1]), "=r"(r[2]), "=r"(r[3]) : "r"(a));
}
__device__ __forceinline__ void mma_bf16(float* d, const uint32_t* a, const uint32_t* b) {
    asm volatile("mma.sync.aligned.m16n8k16.row.col.f32.bf16.bf16.f32 "
                 "{%0,%1,%2,%3}, {%4,%5,%6,%7}, {%8,%9}, {%0,%1,%2,%3};"
                 : "+f"(d[0]), "+f"(d[1]), "+f"(d[2]), "+f"(d[3])
                 : "r"(a[0]), "r"(a[1]), "r"(a[2]), "r"(a[3]), "r"(b[0]), "r"(b[1]));
}
__device__ __forceinline__ void cpa16(uint32_t dst, const void* src) {
    asm volatile("cp.async.cg.shared.global [%0], [%1], 16;" :: "r"(dst), "l"(src));
}
#define CP_COMMIT() asm volatile("cp.async.commit_group;" ::: "memory")
#define CP_WAIT2()  asm volatile("cp.async.wait_group 2;" ::: "memory")

// fp32x4 -> bf16 hi/lo planes (packed as 2x uint2)
__device__ __forceinline__ void split4(float4 v, uint2& hp, uint2& lp) {
    __nv_bfloat16 h0 = __float2bfloat16_rn(v.x), h1 = __float2bfloat16_rn(v.y);
    __nv_bfloat16 h2 = __float2bfloat16_rn(v.z), h3 = __float2bfloat16_rn(v.w);
    __nv_bfloat16 l0 = __float2bfloat16_rn(v.x - __bfloat162float(h0));
    __nv_bfloat16 l1 = __float2bfloat16_rn(v.y - __bfloat162float(h1));
    __nv_bfloat16 l2 = __float2bfloat16_rn(v.z - __bfloat162float(h2));
    __nv_bfloat16 l3 = __float2bfloat16_rn(v.w - __bfloat162float(h3));
    hp.x = (uint32_t)__bfloat16_as_ushort(h0) | ((uint32_t)__bfloat16_as_ushort(h1) << 16);
    hp.y = (uint32_t)__bfloat16_as_ushort(h2) | ((uint32_t)__bfloat16_as_ushort(h3) << 16);
    lp.x = (uint32_t)__bfloat16_as_ushort(l0) | ((uint32_t)__bfloat16_as_ushort(l1) << 16);
    lp.y = (uint32_t)__bfloat16_as_ushort(l2) | ((uint32_t)__bfloat16_as_ushort(l3) << 16);
}
__device__ __forceinline__ void store_hl2(__nv_bfloat16* ph, __nv_bfloat16* pl,
                                          float v0, float v1) {
    __nv_bfloat16 h0 = __float2bfloat16_rn(v0), h1 = __float2bfloat16_rn(v1);
    __nv_bfloat16 l0 = __float2bfloat16_rn(v0 - __bfloat162float(h0));
    __nv_bfloat16 l1 = __float2bfloat16_rn(v1 - __bfloat162float(h1));
    *(uint32_t*)ph = (uint32_t)__bfloat16_as_ushort(h0) | ((uint32_t)__bfloat16_as_ushort(h1) << 16);
    *(uint32_t*)pl = (uint32_t)__bfloat16_as_ushort(l0) | ((uint32_t)__bfloat16_as_ushort(l1) << 16);
}
__device__ __forceinline__ float silumul(float h1, float h3) {
    return (h1 / (1.f + __expf(-h1))) * h3;
}

// ---------------- router (also writes x hi/lo planes) ----------------
__global__ void router_kernel(const float* __restrict__ x,
                              const float* __restrict__ gw,
                              float* __restrict__ out,
                              float* __restrict__ logits) {
    const int t = blockIdx.x;
    const int tid = threadIdx.x;
    const float* xr = x + (size_t)t * HDIM;

    float acc[NEXP];
#pragma unroll
    for (int e = 0; e < NEXP; e++) acc[e] = 0.f;
    for (int h = tid; h < HDIM; h += 128) {
        float xv = xr[h];
        __nv_bfloat16 hb = __float2bfloat16_rn(xv);
        g_xh[(size_t)t * HDIM + h] = hb;
        g_xl[(size_t)t * HDIM + h] = __float2bfloat16_rn(xv - __bfloat162float(hb));
#pragma unroll
        for (int e = 0; e < NEXP; e++) acc[e] += xv * gw[e * HDIM + h];
    }
    __shared__ float red[NEXP][128];
#pragma unroll
    for (int e = 0; e < NEXP; e++) red[e][tid] = acc[e];
    __syncthreads();
    for (int s = 64; s > 0; s >>= 1) {
        if (tid < s) {
#pragma unroll
            for (int e = 0; e < NEXP; e++) red[e][tid] += red[e][tid + s];
        }
        __syncthreads();
    }
    float* orow = out + (size_t)t * HDIM;
    for (int h = tid; h < HDIM; h += 128) orow[h] = 0.f;

    if (tid == 0) {
        float lg[NEXP];
        float mx = -1e30f;
#pragma unroll
        for (int e = 0; e < NEXP; e++) {
            lg[e] = red[e][0];
            logits[t * NEXP + e] = lg[e];
            mx = fmaxf(mx, lg[e]);
        }
        float pe[NEXP];
#pragma unroll
        for (int e = 0; e < NEXP; e++) pe[e] = expf(lg[e] - mx);
        int i1 = 0;
#pragma unroll
        for (int e = 1; e < NEXP; e++) if (pe[e] > pe[i1]) i1 = e;
        int i2 = (i1 == 0) ? 1 : 0;
#pragma unroll
        for (int e = 0; e < NEXP; e++) if (e != i2 && e != i1 && pe[e] > pe[i2]) i2 = e;
        float p1 = pe[i1], p2 = pe[i2];
        float inv = 1.f / (p1 + p2);
        g_topi[t] = make_int2(i1, i2);
        g_topw[t] = make_float2(p1 * inv, p2 * inv);
    }
}

// ---------------- token lists ----------------
__global__ void build_lists() {
    const int tid = threadIdx.x;
    __shared__ int2 stop[TOK];
    __shared__ float2 stw[TOK];
    __shared__ int cnt[NEXP], off[NEXP], pad[NEXP];

    for (int t = tid; t < TOK; t += 64) { stop[t] = g_topi[t]; stw[t] = g_topw[t]; }
    __syncthreads();
    if (tid < NEXP) {
        int c = 0;
        for (int t = 0; t < TOK; t++) {
            int2 ti = stop[t];
            if (ti.x == tid || ti.y == tid) c++;
        }
        cnt[tid] = c;
    }
    __syncthreads();
    if (tid == 0) {
        int o = 0;
        for (int e = 0; e < NEXP; e++) {
            off[e] = o;
            pad[e] = (cnt[e] + BM - 1) & ~(BM - 1);
            for (int tt = o / BM; tt < (o + pad[e]) / BM; tt++) g_tile_expert[tt] = e;
            o += pad[e];
        }
        g_nRowTiles = o / BM;
    }
    __syncthreads();
    if (tid < NEXP) {
        const int e = tid;
        int pos = off[e];
        for (int t = 0; t < TOK; t++) {
            int2 ti = stop[t];
            if (ti.x == e)      { g_ptok[pos] = t; g_pw[pos] = stw[t].x; pos++; }
            else if (ti.y == e) { g_ptok[pos] = t; g_pw[pos] = stw[t].y; pos++; }
        }
        const int end = off[e] + pad[e];
        for (; pos < end; pos++) { g_ptok[pos] = 0; g_pw[pos] = 0.f; }
    }
}

// ================= fused w1/w3 kernel =================
// A: 4-stage cp.async ring, 16KB/stage (AHI 0, ALO 8K within stage)
// B: double buffer, 16KB/buf (B1HI 0, B1LO 4K, B3HI 8K, B3LO 12K)
#define A_ST    16384
#define A_BASE  1024
#define B_BASE1 (1024 + 4 * A_ST)        // 66560
#define B_ST1   16384
#define SM13    (B_BASE1 + 2 * B_ST1)    // 99328
#define NC1     (HDIM / BK)              // 32

__global__ void __launch_bounds__(256, 2)
moe_gemm13(const float* __restrict__ w1,
           const float* __restrict__ w3) {
    const int rt = blockIdx.y;
    if (rt >= g_nRowTiles) return;
    extern __shared__ char smem[];
    const uint32_t sb0 = (uint32_t)__cvta_generic_to_shared(smem);
    const int tid = threadIdx.x, wid = tid >> 5, lane = tid & 31;
    const int wm = wid & 3, wn = wid >> 2;
    const int e  = g_tile_expert[rt];
    const int n0 = blockIdx.x * BN;
    const int r0 = rt * BM;

    int* s_tok = (int*)smem;
    if (tid < BM) s_tok[tid] = g_ptok[r0 + tid];
    __syncthreads();

    const float* w1e = w1 + (size_t)e * FDIM * HDIM;
    const float* w3e = w3 + (size_t)e * FDIM * HDIM;

    // A cp.async role
    const int arow = tid >> 1;
    const int aseg = (tid & 1) * 2;
    const __nv_bfloat16* axh = g_xh + (size_t)s_tok[arow] * HDIM + aseg * 8;
    const __nv_bfloat16* axl = g_xl + (size_t)s_tok[arow] * HDIM + aseg * 8;
    const uint32_t ad0 = SWZ64((uint32_t)(arow * 64 + aseg * 16));
    const uint32_t ad1 = SWZ64((uint32_t)(arow * 64 + aseg * 16 + 16));

    // B staging role
    const int brow = tid >> 2, bcol = (tid & 3) * 8;
    const float* b1p = w1e + (size_t)(n0 + brow) * HDIM + bcol;
    const float* b3p = w3e + (size_t)(n0 + brow) * HDIM + bcol;
    uint32_t boff[2];
#pragma unroll
    for (int j = 0; j < 2; j++) boff[j] = SWZ64((uint32_t)(brow * 64 + (bcol + j * 4) * 2));

    float4 b1R[2], b3R[2];

    // prologue: pre-issue A chunks 0..2 (one commit group each); stage B chunk 0
#pragma unroll
    for (int p = 0; p < 3; p++) {
        uint32_t st = sb0 + A_BASE + p * A_ST;
        const int k0 = p * BK;
        cpa16(st + ad0, axh + k0);
        cpa16(st + ad1, axh + k0 + 8);
        cpa16(st + 8192 + ad0, axl + k0);
        cpa16(st + 8192 + ad1, axl + k0 + 8);
        CP_COMMIT();
    }
    {
#pragma unroll
        for (int j = 0; j < 2; j++) { b1R[j] = *(const float4*)(b1p + j * 4); b3R[j] = *(const float4*)(b3p + j * 4); }
        char* stc = smem + B_BASE1;
        uint2 hp, lp;
#pragma unroll
        for (int j = 0; j < 2; j++) {
            split4(b1R[j], hp, lp); *(uint2*)(stc + boff[j]) = hp;         *(uint2*)(stc + 4096 + boff[j]) = lp;
            split4(b3R[j], hp, lp); *(uint2*)(stc + 8192 + boff[j]) = hp;  *(uint2*)(stc + 12288 + boff[j]) = lp;
        }
    }
    CP_WAIT2();     // chunk 0 landed
    __syncthreads();

    float a1[2][4][4], a3[2][4][4];
#pragma unroll
    for (int m = 0; m < 2; m++)
#pragma unroll
        for (int n = 0; n < 4; n++)
#pragma unroll
            for (int q = 0; q < 4; q++) { a1[m][n][q] = 0.f; a3[m][n][q] = 0.f; }

    for (int c = 0; c < NC1; c++) {
        // issue A for chunk c+3 into stage (c+3)&3
        {
            const int cpf = c + 3;
            if (cpf < NC1) {
                uint32_t st = sb0 + A_BASE + (cpf & 3) * A_ST;
                const int k0 = cpf * BK;
                cpa16(st + ad0, axh + k0);
                cpa16(st + ad1, axh + k0 + 8);
                cpa16(st + 8192 + ad0, axl + k0);
                cpa16(st + 8192 + ad1, axl + k0 + 8);
            }
            CP_COMMIT();
        }
        if (c + 1 < NC1) {
            const int kn = (c + 1) * BK;
#pragma unroll
            for (int j = 0; j < 2; j++) { b1R[j] = *(const float4*)(b1p + kn + j * 4); b3R[j] = *(const float4*)(b3p + kn + j * 4); }
        }

        const uint32_t sa = sb0 + A_BASE + (c & 3) * A_ST;
        const uint32_t sbb = sb0 + B_BASE1 + (c & 1) * B_ST1;
#pragma unroll
        for (int s = 0; s < 2; s++) {
            const int ks = s * 16;
            uint32_t ah[2][4], al[2][4];
#pragma unroll
            for (int mt = 0; mt < 2; mt++) {
                uint32_t ro = SWZ64((uint32_t)((wm * 32 + mt * 16 + (lane & 15)) * 64 + (ks + (lane >> 4) * 8) * 2));
                ldmx4(ah[mt], sa + ro);
                ldmx4(al[mt], sa + 8192 + ro);
            }
            uint32_t b1h[2][4], b1l[2][4], b3h[2][4], b3l[2][4];
#pragma unroll
            for (int np = 0; np < 2; np++) {
                uint32_t ro = SWZ64((uint32_t)((wn * 32 + np * 16 + ((lane >> 4) & 1) * 8 + (lane & 7)) * 64 +
                                               (ks + ((lane >> 3) & 1) * 8) * 2));
                ldmx4(b1h[np], sbb + ro);
                ldmx4(b1l[np], sbb + 4096 + ro);
                ldmx4(b3h[np], sbb + 8192 + ro);
                ldmx4(b3l[np], sbb + 12288 + ro);
            }
#pragma unroll
            for (int mt = 0; mt < 2; mt++)
#pragma unroll
                for (int np = 0; np < 2; np++)
#pragma unroll
                    for (int h = 0; h < 2; h++) {
                        const int nt2 = np * 2 + h;
                        mma_bf16(a1[mt][nt2], ah[mt], &b1h[np][h * 2]);
                        mma_bf16(a1[mt][nt2], ah[mt], &b1l[np][h * 2]);
                        mma_bf16(a1[mt][nt2], al[mt], &b1h[np][h * 2]);
                        mma_bf16(a3[mt][nt2], ah[mt], &b3h[np][h * 2]);
                        mma_bf16(a3[mt][nt2], ah[mt], &b3l[np][h * 2]);
                        mma_bf16(a3[mt][nt2], al[mt], &b3h[np][h * 2]);
                    }
        }
        if (c + 1 < NC1) {
            char* stc = smem + B_BASE1 + ((c + 1) & 1) * B_ST1;
            uint2 hp, lp;
#pragma unroll
            for (int j = 0; j < 2; j++) {
                split4(b1R[j], hp, lp); *(uint2*)(stc + boff[j]) = hp;         *(uint2*)(stc + 4096 + boff[j]) = lp;
                split4(b3R[j], hp, lp); *(uint2*)(stc + 8192 + boff[j]) = hp;  *(uint2*)(stc + 12288 + boff[j]) = lp;
            }
        }
        CP_WAIT2();       // chunk c+1's A ring stage is landed
        __syncthreads();
    }

    // epilogue: act = silu(h1)*h3 -> hi/lo planes
#pragma unroll
    for (int mt = 0; mt < 2; mt++)
#pragma unroll
        for (int nt2 = 0; nt2 < 4; nt2++) {
            const int row = r0 + wm * 32 + mt * 16 + (lane >> 2);
            const int col = n0 + wn * 32 + nt2 * 8 + 2 * (lane & 3);
            store_hl2(g_ah + (size_t)row * FDIM + col, g_al + (size_t)row * FDIM + col,
                      silumul(a1[mt][nt2][0], a3[mt][nt2][0]),
                      silumul(a1[mt][nt2][1], a3[mt][nt2][1]));
            store_hl2(g_ah + (size_t)(row + 8) * FDIM + col, g_al + (size_t)(row + 8) * FDIM + col,
                      silumul(a1[mt][nt2][2], a3[mt][nt2][2]),
                      silumul(a1[mt][nt2][3], a3[mt][nt2][3]));
        }
}

// ================= w2 kernel =================
// A: 4-stage cp.async ring 16KB/stage; B: double buffer 8KB/buf (BHI 0, BLO 4K)
#define B_BASE2 (1024 + 4 * A_ST)        // 66560
#define B_ST2   8192
#define SM2     (B_BASE2 + 2 * B_ST2)    // 82944
#define NC2     (FDIM / BK)              // 112

__global__ void __launch_bounds__(256, 2)
moe_gemm2(const float* __restrict__ w2, float* __restrict__ out) {
    const int rt = blockIdx.y;
    if (rt >= g_nRowTiles) return;
    extern __shared__ char smem[];
    const uint32_t sb0 = (uint32_t)__cvta_generic_to_shared(smem);
    const int tid = threadIdx.x, wid = tid >> 5, lane = tid & 31;
    const int wm = wid & 3, wn = wid >> 2;
    const int e  = g_tile_expert[rt];
    const int n0 = blockIdx.x * BN;
    const int r0 = rt * BM;

    int*   s_tok = (int*)smem;
    float* s_w   = (float*)(smem + 512);
    if (tid < BM) { s_tok[tid] = g_ptok[r0 + tid]; s_w[tid] = g_pw[r0 + tid]; }
    __syncthreads();

    const float* w2e = w2 + (size_t)e * HDIM * FDIM;

    const int arow = tid >> 1;
    const int aseg = (tid & 1) * 2;
    const __nv_bfloat16* aph = g_ah + (size_t)(r0 + arow) * FDIM + aseg * 8;
    const __nv_bfloat16* apl = g_al + (size_t)(r0 + arow) * FDIM + aseg * 8;
    const uint32_t ad0 = SWZ64((uint32_t)(arow * 64 + aseg * 16));
    const uint32_t ad1 = SWZ64((uint32_t)(arow * 64 + aseg * 16 + 16));

    const int brow = tid >> 2, bcol = (tid & 3) * 8;
    const float* bp = w2e + (size_t)(n0 + brow) * FDIM + bcol;
    uint32_t boff[2];
#pragma unroll
    for (int j = 0; j < 2; j++) boff[j] = SWZ64((uint32_t)(brow * 64 + (bcol + j * 4) * 2));

    float4 bR[2];

    // prologue
#pragma unroll
    for (int p = 0; p < 3; p++) {
        uint32_t st = sb0 + A_BASE + p * A_ST;
        const int k0 = p * BK;
        cpa16(st + ad0, aph + k0);
        cpa16(st + ad1, aph + k0 + 8);
        cpa16(st + 8192 + ad0, apl + k0);
        cpa16(st + 8192 + ad1, apl + k0 + 8);
        CP_COMMIT();
    }
    {
#pragma unroll
        for (int j = 0; j < 2; j++) bR[j] = *(const float4*)(bp + j * 4);
        char* stc = smem + B_BASE2;
        uint2 hp, lp;
#pragma unroll
        for (int j = 0; j < 2; j++) { split4(bR[j], hp, lp); *(uint2*)(stc + boff[j]) = hp; *(uint2*)(stc + 4096 + boff[j]) = lp; }
    }
    CP_WAIT2();
    __syncthreads();

    float acc[2][4][4];
#pragma unroll
    for (int m = 0; m < 2; m++)
#pragma unroll
        for (int n = 0; n < 4; n++)
#pragma unroll
            for (int q = 0; q < 4; q++) acc[m][n][q] = 0.f;

    for (int c = 0; c < NC2; c++) {
        {
            const int cpf = c + 3;
            if (cpf < NC2) {
                uint32_t st = sb0 + A_BASE + (cpf & 3) * A_ST;
                const int k0 = cpf * BK;
                cpa16(st + ad0, aph + k0);
                cpa16(st + ad1, aph + k0 + 8);
                cpa16(st + 8192 + ad0, apl + k0);
                cpa16(st + 8192 + ad1, apl + k0 + 8);
            }
            CP_COMMIT();
        }
        if (c + 1 < NC2) {
            const int kn = (c + 1) * BK;
#pragma unroll
            for (int j = 0; j < 2; j++) bR[j] = *(const float4*)(bp + kn + j * 4);
        }

        const uint32_t sa = sb0 + A_BASE + (c & 3) * A_ST;
        const uint32_t sbb = sb0 + B_BASE2 + (c & 1) * B_ST2;
#pragma unroll
        for (int s = 0; s < 2; s++) {
            const int ks = s * 16;
            uint32_t ah[2][4], al[2][4];
#pragma unroll
            for (int mt = 0; mt < 2; mt++) {
                uint32_t ro = SWZ64((uint32_t)((wm * 32 + mt * 16 + (lane & 15)) * 64 + (ks + (lane >> 4) * 8) * 2));
                ldmx4(ah[mt], sa + ro);
                ldmx4(al[mt], sa + 8192 + ro);
            }
            uint32_t bh[2][4], bl[2][4];
#pragma unroll
            for (int np = 0; np < 2; np++) {
                uint32_t ro = SWZ64((uint32_t)((wn * 32 + np * 16 + ((lane >> 4) & 1) * 8 + (lane & 7)) * 64 +
                                               (ks + ((lane >> 3) & 1) * 8) * 2));
                ldmx4(bh[np], sbb + ro);
                ldmx4(bl[np], sbb + 4096 + ro);
            }
#pragma unroll
            for (int mt = 0; mt < 2; mt++)
#pragma unroll
                for (int np = 0; np < 2; np++)
#pragma unroll
                    for (int h = 0; h < 2; h++) {
                        const int nt2 = np * 2 + h;
                        mma_bf16(acc[mt][nt2], ah[mt], &bh[np][h * 2]);
                        mma_bf16(acc[mt][nt2], ah[mt], &bl[np][h * 2]);
                        mma_bf16(acc[mt][nt2], al[mt], &bh[np][h * 2]);
                    }
        }
        if (c + 1 < NC2) {
            char* stc = smem + B_BASE2 + ((c + 1) & 1) * B_ST2;
            uint2 hp, lp;
#pragma unroll
            for (int j = 0; j < 2; j++) { split4(bR[j], hp, lp); *(uint2*)(stc + boff[j]) = hp; *(uint2*)(stc + 4096 + boff[j]) = lp; }
        }
        CP_WAIT2();
        __syncthreads();
    }

    // epilogue: weighted atomic combine
#pragma unroll
    for (int mt = 0; mt < 2; mt++) {
        const int lr0 = wm * 32 + mt * 16 + (lane >> 2);
        const int tok0 = s_tok[lr0];     const float wt0 = s_w[lr0];
        const int tok1 = s_tok[lr0 + 8]; const float wt1 = s_w[lr0 + 8];
#pragma unroll
        for (int nt2 = 0; nt2 < 4; nt2++) {
            const int col = n0 + wn * 32 + nt2 * 8 + 2 * (lane & 3);
            float* o0 = out + (size_t)tok0 * HDIM + col;
            float* o1 = out + (size_t)tok1 * HDIM + col;
            atomicAdd(o0,     wt0 * acc[mt][nt2][0]);
            atomicAdd(o0 + 1, wt0 * acc[mt][nt2][1]);
            atomicAdd(o1,     wt1 * acc[mt][nt2][2]);
            atomicAdd(o1 + 1, wt1 * acc[mt][nt2][3]);
        }
    }
}

// ---------------- launch ----------------
extern "C" void kernel_launch(void* const* d_in, const int* in_sizes, int n_in,
                              void* d_out, int out_size) {
    const float* x  = (const float*)d_in[0];
    const float* gw = (const float*)d_in[1];
    const float* w1 = (const float*)d_in[2];
    const float* w2 = (const float*)d_in[3];
    const float* w3 = (const float*)d_in[4];

    float* out    = (float*)d_out;
    float* logits = out + (size_t)TOK * HDIM;

    cudaFuncSetAttribute(moe_gemm13, cudaFuncAttributeMaxDynamicSharedMemorySize, SM13);
    cudaFuncSetAttribute(moe_gemm2,  cudaFuncAttributeMaxDynamicSharedMemorySize, SM2);

    router_kernel<<<TOK, 128>>>(x, gw, out, logits);
    build_lists<<<1, 64>>>();
    moe_gemm13<<<dim3(FDIM / BN, MAXTILES), 256, SM13>>>(w1, w3);
    moe_gemm2<<<dim3(HDIM / BN, MAXTILES), 256, SM2>>>(w2, out);
}